// round 11
// baseline (speedup 1.0000x reference)
#include <cuda_runtime.h>

#define CCX 64
#define HH 255
#define WW 256
#define FF 129
#define SP (FF*HH)       /* 32895 */
#define NVB 8

__device__ float g_Y1r[(size_t)4*CCX*FF*WW];
__device__ float g_Y1i[(size_t)4*CCX*FF*WW];
__device__ float g_Z  [(size_t)NVB*128*SP];
__device__ float g_Yc [(size_t)NVB*128*SP];
__device__ float g_Vr [(size_t)NVB*CCX*128*FF];
__device__ float g_Vi [(size_t)NVB*CCX*128*FF];
__device__ float g_Mwc[WW*FF], g_Mws[WW*FF];
__device__ float g_Mhc[HH*HH], g_Mhs[HH*HH];
__device__ float g_Mic[FF*WW], g_Mis[FF*WW];
__device__ float g_mu[NVB*16], g_rs[NVB*16];

__device__ __forceinline__ unsigned long long pack2(float v) {
  unsigned long long r; asm("mov.b64 %0, {%1, %1};" : "=l"(r) : "f"(v)); return r;
}
__device__ __forceinline__ void fma2(unsigned long long& d, unsigned long long a,
                                     unsigned long long b) {
  asm("fma.rn.f32x2 %0, %1, %2, %0;" : "+l"(d) : "l"(a), "l"(b));
}
__device__ __forceinline__ float2 unpk(unsigned long long v) {
  float2 f; asm("mov.b64 {%0, %1}, %2;" : "=f"(f.x), "=f"(f.y) : "l"(v)); return f;
}

__global__ void init_mats() {
  int i = blockIdx.x * blockDim.x + threadIdx.x;
  const float TP = 6.2831853071795864769f;
  if (i < WW*FF) {
    int w = i / FF, f = i - w*FF;
    int t = (w*f) & 255;
    float sn, cs; sincosf((float)t * (TP/256.f), &sn, &cs);
    g_Mwc[i] = cs; g_Mws[i] = sn;
  }
  if (i < FF*WW) {
    int f = i >> 8, w = i & 255;
    int t = (f*w) & 255;
    float sn, cs; sincosf((float)t * (TP/256.f), &sn, &cs);
    float amp = (f == 0 || f == 128) ? (1.f/256.f) : (2.f/256.f);
    g_Mic[i] = amp*cs; g_Mis[i] = amp*sn;
  }
  if (i < HH*HH) {
    int h = i / HH, k = i - h*HH;
    int t = (h*k) % HH;
    float sn, cs; sincosf((float)t * (TP/255.f), &sn, &cs);
    g_Mhc[i] = cs; g_Mhs[i] = sn;
  }
}

// Nyquist column of W-rFFT (f=128): yr = sum x*(-1)^w, yi = 0
__global__ void nyq_w(const float* __restrict__ x) {
  int m = blockIdx.x * 256 + threadIdx.x;       // 65536 rows
  const float4* xr = (const float4*)(x + (size_t)m * WW);
  float s = 0.f;
  #pragma unroll 8
  for (int q = 0; q < 64; q++) { float4 v = xr[q]; s += (v.x - v.y) + (v.z - v.w); }
  size_t co = ((size_t)(m >> 8) * FF + 128) * WW + (m & 255);
  g_Y1r[co] = s; g_Y1i[co] = 0.f;
}

// Unified packed GEMM. Tile 128(M) x 128(N floats), 256 thr, micro 8x8, KT=8.
// cr += ar*bc + ai*bs ; ci += ai*bc - ar*bs   (E folded into bs at smem store)
template<int STEP>
__global__ void __launch_bounds__(256) dft_gemm(const float* __restrict__ Aext,
                                                const float* __restrict__ bias,
                                                float* __restrict__ Cext)
{
  constexpr bool HAS_AI  = (STEP==2 || STEP==4 || STEP==5);
  constexpr bool WANT_CI = (STEP==1 || STEP==2 || STEP==4);
  constexpr bool HAS_BS  = (STEP!=3);
  constexpr float BSGN = (STEP==4 || STEP==5) ? -1.0f : 1.0f;
  constexpr float SCALE = (STEP==4) ? (1.0f/255.0f) : 1.0f;
  constexpr int N = (STEP==1) ? 128 : (STEP==2) ? HH : (STEP==3) ? SP :
                    (STEP==4) ? 128 : WW;
  constexpr int K = (STEP==1) ? WW : (STEP==2 || STEP==4) ? HH :
                    (STEP==3) ? 128 : FF;

  const float* Ar0; const float* Ai0 = nullptr;
  const float* Bc0; const float* Bs0 = nullptr;
  float* Cr0; float* Ci0 = nullptr;
  if constexpr (STEP==1) { Ar0=Aext; Bc0=g_Mwc; Bs0=g_Mws; Cr0=g_Y1r; Ci0=g_Y1i; }
  else if constexpr (STEP==2) { Ar0=g_Y1r; Ai0=g_Y1i; Bc0=g_Mhc; Bs0=g_Mhs;
                                Cr0=g_Z; Ci0=g_Z + (size_t)64*SP; }
  else if constexpr (STEP==3) { Ar0=Aext; Bc0=g_Z; Cr0=g_Yc; }
  else if constexpr (STEP==4) { Ar0=g_Yc; Ai0=g_Yc + (size_t)64*SP; Bc0=g_Mhc; Bs0=g_Mhs;
                                Cr0=g_Vr; Ci0=g_Vi; }
  else                        { Ar0=g_Vr; Ai0=g_Vi; Bc0=g_Mic; Bs0=g_Mis; Cr0=Cext; }

  __shared__ __align__(16) float sAr[8][128];
  __shared__ __align__(16) float sAi[HAS_AI ? 8 : 1][128];
  __shared__ __align__(16) float sBc[8][128];
  __shared__ __align__(16) float sBs[HAS_BS ? 8 : 1][128];

  const int tid = threadIdx.x;
  const int m0 = blockIdx.y * 128, n0 = blockIdx.x * 128;

  // A loader: 2 threads per row, 4 consecutive k each
  const int lr = tid >> 1, lk = (tid & 1) * 4;
  const int mA = m0 + lr;
  long aro = 0, aio = 0;
  if constexpr (STEP==1) aro = (long)mA * WW;
  else if constexpr (STEP==2) {
    int f = mA % FF; int t2 = mA / FF; int c = t2 % CCX; int vb = t2 / CCX;
    aro = ((long)((vb & 3)*CCX + c)*FF + f)*WW + (vb >> 2); aio = aro;
  } else if constexpr (STEP==3) aro = (long)(mA & 127) * 128;
  else if constexpr (STEP==4) {
    int f = mA % FF; int t2 = mA / FF; int c = t2 % CCX; int vb = t2 / CCX;
    aro = (long)(vb*128 + c)*SP + (long)f*HH; aio = aro + (long)64*SP;
  } else { aro = (long)mA * FF; aio = aro; }
  const float* ArP = Ar0 + aro;
  const float* AiP = HAS_AI ? ((STEP==2) ? Ai0 + aro : (STEP==4) ? Ar0 + aio : Ai0 + aio)
                            : nullptr;

  // B loader: 8 k-rows x 128 n, 4 per thread
  const int kb = tid >> 5, nq = (tid & 31) * 4;
  constexpr int LDBV = (STEP==1) ? FF : (STEP==2 || STEP==4) ? HH :
                       (STEP==3) ? SP : WW;
  long b_base = 0;
  if constexpr (STEP==3) b_base = (long)blockIdx.y * 128 * SP;
  if constexpr (STEP==4) b_base = (long)(m0 / (4*CCX*FF)) * 127;   // v*127 col offset

  const int ty8 = (tid >> 4) * 8;
  const int tx8 = (tid & 15) * 8;

  unsigned long long cr[8][4], ci[WANT_CI ? 8 : 1][WANT_CI ? 4 : 1];
  #pragma unroll
  for (int i = 0; i < 8; i++)
    #pragma unroll
    for (int p = 0; p < 4; p++) { cr[i][p] = 0ull; if constexpr (WANT_CI) ci[i][p] = 0ull; }

  float rAr[4], rAi[4], rBc[4], rBs[4];
  #pragma unroll
  for (int j = 0; j < 4; j++) {
    int kk = lk + j;
    rAr[j] = (kk < K) ? ArP[kk] : 0.f;
    if constexpr (HAS_AI) rAi[j] = (kk < K) ? AiP[kk] : 0.f;
  }
  #pragma unroll
  for (int j = 0; j < 4; j++) {
    int n = n0 + nq + j;
    bool ok = (kb < K && n < N);
    long bo = (long)kb * LDBV + n + b_base;
    rBc[j] = ok ? Bc0[bo] : 0.f;
    if constexpr (HAS_BS) rBs[j] = ok ? BSGN * Bs0[bo] : 0.f;
  }

  for (int k0 = 0; k0 < K; k0 += 8) {
    #pragma unroll
    for (int j = 0; j < 4; j++) {
      sAr[lk + j][lr] = rAr[j];
      if constexpr (HAS_AI) sAi[lk + j][lr] = rAi[j];
      sBc[kb][nq + j] = rBc[j];
      if constexpr (HAS_BS) sBs[kb][nq + j] = rBs[j];
    }
    __syncthreads();

    if (k0 + 8 < K) {
      #pragma unroll
      for (int j = 0; j < 4; j++) {
        int kk = k0 + 8 + lk + j;
        rAr[j] = (kk < K) ? ArP[kk] : 0.f;
        if constexpr (HAS_AI) rAi[j] = (kk < K) ? AiP[kk] : 0.f;
      }
      int kk = k0 + 8 + kb;
      #pragma unroll
      for (int j = 0; j < 4; j++) {
        int n = n0 + nq + j;
        bool ok = (kk < K && n < N);
        long bo = (long)kk * LDBV + n + b_base;
        rBc[j] = ok ? Bc0[bo] : 0.f;
        if constexpr (HAS_BS) rBs[j] = ok ? BSGN * Bs0[bo] : 0.f;
      }
    }

    #pragma unroll
    for (int kk = 0; kk < 8; kk++) {
      float4 a0 = *(const float4*)&sAr[kk][ty8];
      float4 a1 = *(const float4*)&sAr[kk][ty8 + 4];
      float av[8] = {a0.x,a0.y,a0.z,a0.w,a1.x,a1.y,a1.z,a1.w};
      float iv[8];
      if constexpr (HAS_AI) {
        float4 i0 = *(const float4*)&sAi[kk][ty8];
        float4 i1 = *(const float4*)&sAi[kk][ty8 + 4];
        iv[0]=i0.x; iv[1]=i0.y; iv[2]=i0.z; iv[3]=i0.w;
        iv[4]=i1.x; iv[5]=i1.y; iv[6]=i1.z; iv[7]=i1.w;
      }
      unsigned long long bc2[4], bs2[4];
      {
        ulonglong2 t0 = *(const ulonglong2*)&sBc[kk][tx8];
        ulonglong2 t1 = *(const ulonglong2*)&sBc[kk][tx8 + 4];
        bc2[0]=t0.x; bc2[1]=t0.y; bc2[2]=t1.x; bc2[3]=t1.y;
        if constexpr (HAS_BS) {
          ulonglong2 u0 = *(const ulonglong2*)&sBs[kk][tx8];
          ulonglong2 u1 = *(const ulonglong2*)&sBs[kk][tx8 + 4];
          bs2[0]=u0.x; bs2[1]=u0.y; bs2[2]=u1.x; bs2[3]=u1.y;
        }
      }
      #pragma unroll
      for (int i = 0; i < 8; i++) {
        unsigned long long pr = pack2(av[i]);
        unsigned long long pi, nr;
        if constexpr (HAS_AI) pi = pack2(iv[i]);
        if constexpr (WANT_CI) nr = pr ^ 0x8000000080000000ull;
        #pragma unroll
        for (int p = 0; p < 4; p++) {
          fma2(cr[i][p], pr, bc2[p]);
          if constexpr (HAS_AI && HAS_BS) fma2(cr[i][p], pi, bs2[p]);
          if constexpr (WANT_CI) {
            if constexpr (HAS_AI) fma2(ci[i][p], pi, bc2[p]);
            fma2(ci[i][p], nr, bs2[p]);
          }
        }
      }
    }
    __syncthreads();
  }

  #pragma unroll
  for (int i = 0; i < 8; i++) {
    int m = m0 + ty8 + i;
    #pragma unroll
    for (int p = 0; p < 4; p++) {
      float2 v = unpk(cr[i][p]);
      float2 w;
      if constexpr (WANT_CI) w = unpk(ci[i][p]);
      int n = n0 + tx8 + 2*p;
      if constexpr (STEP==1) {
        long co = ((long)(m >> 8)*FF + n)*WW + (m & 255);
        g_Y1r[co] = v.x;          g_Y1i[co] = w.x;
        g_Y1r[co + WW] = v.y;     g_Y1i[co + WW] = w.y;
      } else if constexpr (STEP==2) {
        int f = m % FF; int t2 = m / FF; int c = t2 % CCX; int vb = t2 / CCX;
        long co = (long)vb*128*SP + (long)c*SP + (long)f*HH + n;
        if (n < N)     { Cr0[co] = v.x;     Ci0[co] = w.x; }
        if (n + 1 < N) { Cr0[co + 1] = v.y; Ci0[co + 1] = w.y; }
      } else if constexpr (STEP==3) {
        float b = bias[m & 127];
        long co = (long)blockIdx.y*128*SP + (long)(m & 127)*SP + n;
        if (n < N)     Cr0[co] = v.x + b;
        if (n + 1 < N) Cr0[co + 1] = v.y + b;
      } else if constexpr (STEP==4) {
        long co = ((long)(m / FF)*128 + n)*FF + (m % FF);
        Cr0[co] = v.x * SCALE;       Ci0[co] = w.x * SCALE;
        Cr0[co + FF] = v.y * SCALE;  Ci0[co + FF] = w.y * SCALE;
      } else {
        int hq = m & 127; int t2 = m >> 7; int c = t2 % CCX; int vb = t2 / CCX;
        long co = ((long)((vb & 3)*CCX + c)*WW + (hq + (vb >> 2)*128))*WW + n;
        Cr0[co] = v.x; Cr0[co + 1] = v.y;
      }
    }
  }
}

// ---------------- GroupNorm ----------------
__global__ void __launch_bounds__(1024) gn_stats() {
  const int tid = threadIdx.x;
  const long base = (long)blockIdx.x * 8 * SP;
  const int LEN = 8 * SP;
  double s = 0.0, q = 0.0;
  for (int i = tid; i < LEN; i += 1024) {
    float v = g_Yc[base + i];
    s += (double)v; q += (double)v * (double)v;
  }
  for (int o = 16; o; o >>= 1) {
    s += __shfl_down_sync(0xffffffffu, s, o);
    q += __shfl_down_sync(0xffffffffu, q, o);
  }
  __shared__ double ss[32], sq[32];
  if ((tid & 31) == 0) { ss[tid >> 5] = s; sq[tid >> 5] = q; }
  __syncthreads();
  if (tid == 0) {
    double S = 0.0, Q = 0.0;
    for (int w = 0; w < 32; w++) { S += ss[w]; Q += sq[w]; }
    double mu = S / LEN, var = Q / LEN - mu * mu;
    g_mu[blockIdx.x] = (float)mu;
    g_rs[blockIdx.x] = (float)(1.0 / sqrt(var + 1e-5));
  }
}

__global__ void __launch_bounds__(256) gn_norm(const float* __restrict__ gamma,
                                               const float* __restrict__ beta) {
  long i = (long)blockIdx.x * 256 + threadIdx.x;
  if (i >= (long)NVB * 128 * SP) return;
  int ch = (int)((i / SP) & 127);
  int sidx = (int)(i / ((long)8 * SP));
  float v = (g_Yc[i] - g_mu[sidx]) * g_rs[sidx] * gamma[ch] + beta[ch];
  g_Yc[i] = fmaxf(v, 0.f);
}

extern "C" void kernel_launch(void* const* d_in, const int* in_sizes, int n_in,
                              void* d_out, int out_size) {
  const float* x      = (const float*)d_in[0];
  const float* conv_w = (const float*)d_in[1];
  const float* conv_b = (const float*)d_in[2];
  const float* gamma  = (const float*)d_in[3];
  const float* beta   = (const float*)d_in[4];
  float* out = (float*)d_out;

  init_mats<<<(HH*HH + 255) / 256, 256>>>();
  nyq_w<<<256, 256>>>(x);
  // 1: rFFT-W   M=65536 N=128 K=256
  dft_gemm<1><<<dim3(1, 512), 256>>>(x, nullptr, nullptr);
  // 2: fwd DFT-H   M=66048 N=255 K=255
  dft_gemm<2><<<dim3(2, 516), 256>>>(nullptr, nullptr, nullptr);
  // 3: 1x1 conv   M=1024 N=32895 K=128
  dft_gemm<3><<<dim3((SP + 127) / 128, 8), 256>>>(conv_w, conv_b, nullptr);
  gn_stats<<<NVB*16, 1024>>>();
  gn_norm<<<(int)(((long)NVB*128*SP + 255) / 256), 256>>>(gamma, beta);
  // 4: inv DFT-H   M=66048 N=128 K=255
  dft_gemm<4><<<dim3(1, 516), 256>>>(nullptr, nullptr, nullptr);
  // 5: irFFT-W -> out   M=65536 N=256 K=129
  dft_gemm<5><<<dim3(2, 512), 256>>>(nullptr, nullptr, out);
}